// round 17
// baseline (speedup 1.0000x reference)
#include <cuda_runtime.h>
#include <cuda_fp16.h>
#include <cstdint>
#include <cstddef>

// Problem constants
#define T_TOK 2048
#define D_DIM 512
#define H_DIM 2048
#define N_EXP 8
#define BM 64
#define BN 256
#define BK 64                  // K elements per chunk (4 k16 steps)
#define PAD_ROWS 2560
#define MAX_TILES 40
#define NTHREADS 256

// smem layout
#define A_ROW_H 72             // 64 k-halves + 8 pad (fp16 A)
#define B_ROW_F 260            // 256 n-floats + 4 pad (fp32 B, GEMM1)
#define B_ROW_H 264            // 256 n-halves + 8 pad (fp16 B, GEMM2)
#define A_STAGE_BYTES (BM * A_ROW_H * 2)          // 9216
#define B1_STAGE_BYTES (BK * B_ROW_F * 4)         // 66560
#define B2_STAGE_BYTES (BK * B_ROW_H * 2)         // 33792
#define STAGES 3
#define SMEM1_BYTES (STAGES * (A_STAGE_BYTES + B1_STAGE_BYTES))   // 227328
#define SMEM2_BYTES (STAGES * (A_STAGE_BYTES + B2_STAGE_BYTES))   // 129024

// GEMM2 split-K: 32 BK-chunks -> 16/16
#define NSPLIT 2

#define NW_X  (T_TOK * D_DIM / 2)
#define W_PE  ((size_t)D_DIM * H_DIM)          // fp32 elems per expert
#define NW_PE (D_DIM * H_DIM / 2)              // fp16 words per expert
#define NW_W  (N_EXP * NW_PE)                  // total W2 fp16 words
#define NU2   (NW_W / 2)                       // uint2 elements of g_w2h
#define NCTA1 (MAX_TILES * (H_DIM / BN))       // 320 GEMM1 CTAs
#define PER_CTA ((NU2 + NCTA1 - 1) / NCTA1)    // 6554

// Scratch
__device__ int      g_perm[PAD_ROWS];
__device__ int      g_tile_expert[MAX_TILES + 8];
__device__ uint32_t g_xh[NW_X];                      // x fp16 [t][k] pair-packed
__device__ uint32_t g_w2h[NW_W];                     // W2 fp16 [e][k][n] (piggyback)
__device__ uint32_t g_hh[(size_t)PAD_ROWS * (H_DIM / 2)];  // h fp16 [row][k]
__device__ float    g_ffn[NSPLIT][(size_t)T_TOK * D_DIM];

__device__ __forceinline__ void cp16(uint32_t dst, const void* src, bool pred) {
    int sz = pred ? 16 : 0;
    asm volatile("cp.async.cg.shared.global [%0], [%1], 16, %2;\n"
                 :: "r"(dst), "l"(src), "r"(sz));
}
__device__ __forceinline__ void cp_commit() { asm volatile("cp.async.commit_group;\n"); }
template <int N> __device__ __forceinline__ void cp_wait() {
    asm volatile("cp.async.wait_group %0;\n" :: "n"(N));
}

__device__ __forceinline__ void ldsm4(uint32_t* r, uint32_t a) {
    asm volatile("ldmatrix.sync.aligned.m8n8.x4.shared.b16 {%0,%1,%2,%3}, [%4];"
                 : "=r"(r[0]), "=r"(r[1]), "=r"(r[2]), "=r"(r[3]) : "r"(a));
}
__device__ __forceinline__ void ldsm4t(uint32_t* r, uint32_t a) {
    asm volatile("ldmatrix.sync.aligned.m8n8.x4.trans.shared.b16 {%0,%1,%2,%3}, [%4];"
                 : "=r"(r[0]), "=r"(r[1]), "=r"(r[2]), "=r"(r[3]) : "r"(a));
}

__device__ __forceinline__ void mma16(float* c,
                                      uint32_t a0, uint32_t a1, uint32_t a2, uint32_t a3,
                                      uint32_t b0, uint32_t b1) {
    asm("mma.sync.aligned.m16n8k16.row.col.f32.f16.f16.f32 "
        "{%0,%1,%2,%3}, {%4,%5,%6,%7}, {%8,%9}, {%0,%1,%2,%3};\n"
        : "+f"(c[0]), "+f"(c[1]), "+f"(c[2]), "+f"(c[3])
        : "r"(a0), "r"(a1), "r"(a2), "r"(a3), "r"(b0), "r"(b1));
}

__device__ __forceinline__ uint32_t pack2(float a, float b) {
    __half2 h = __floats2half2_rn(a, b);
    return *reinterpret_cast<uint32_t*>(&h);
}

// ---------------------------------------------------------------------------
// Setup: bins -> histogram -> padded (to 64) grouped permutation + tile table
// ---------------------------------------------------------------------------
__global__ void setup_kernel(const int* __restrict__ orig, const int* __restrict__ hmap) {
    __shared__ int cnt[N_EXP];
    __shared__ int padoff[N_EXP];
    __shared__ int scat[N_EXP];
    int tid = threadIdx.x;

    if (tid < N_EXP) cnt[tid] = 0;
    __syncthreads();

    for (int t = tid; t < T_TOK; t += 256) {
        int b = hmap[orig[t]];
        atomicAdd(&cnt[b], 1);
    }
    for (int i = tid; i < PAD_ROWS; i += 256) g_perm[i] = -1;
    if (tid < MAX_TILES + 8) g_tile_expert[tid] = -1;
    __syncthreads();

    if (tid == 0) {
        int tile = 0;
        for (int e = 0; e < N_EXP; e++) {
            padoff[e] = tile * BM;
            scat[e] = 0;
            int nt = (cnt[e] + BM - 1) / BM;
            for (int i = 0; i < nt; i++) g_tile_expert[tile++] = e;
        }
    }
    __syncthreads();

    for (int t = tid; t < T_TOK; t += 256) {
        int b = hmap[orig[t]];
        int r = atomicAdd(&scat[b], 1);
        g_perm[padoff[b] + r] = t;
    }
}

// ---------------------------------------------------------------------------
// Convert x only: fp32 -> fp16 pair pack
// ---------------------------------------------------------------------------
__global__ void convert_x_kernel(const float* __restrict__ x) {
    int id = blockIdx.x * 256 + threadIdx.x;       // 2 words / thread
    if (id < NW_X / 2) {
        float4 v = *((const float4*)x + id);
        uint2 o; o.x = pack2(v.x, v.y); o.y = pack2(v.z, v.w);
        *((uint2*)g_xh + id) = o;
    }
}

// ---------------------------------------------------------------------------
// W2 slice conversion (runs inside GEMM1): 8-wide prefetch batches
// ---------------------------------------------------------------------------
__device__ __forceinline__ void convert_w2_slice(const float* __restrict__ W2,
                                                 int flat_cta, int tid) {
    int s_base = flat_cta * PER_CTA;
    int s_end = s_base + PER_CTA;
    if (s_end > NU2) s_end = NU2;
    for (int i0 = s_base + tid; i0 < s_end; i0 += NTHREADS * 8) {
        float4 v[8];
        int n = 0;
#pragma unroll
        for (int j = 0; j < 8; ++j) {
            int i = i0 + j * NTHREADS;
            if (i < s_end) { v[j] = *((const float4*)W2 + i); n = j + 1; }
        }
#pragma unroll
        for (int j = 0; j < 8; ++j) {
            int i = i0 + j * NTHREADS;
            if (j < n && i < s_end) {
                uint2 o; o.x = pack2(v[j].x, v[j].y); o.y = pack2(v[j].z, v[j].w);
                *((uint2*)g_w2h + i) = o;
            }
        }
    }
}

// ---------------------------------------------------------------------------
// Compute paths: warp tile 32x64, 4 k16 steps.
// G1: A via ldmatrix (fp16), B built from fp32 smem (LDS + cvt)
// G2: A via ldmatrix (fp16), B via ldmatrix.trans (fp16)
// ---------------------------------------------------------------------------
__device__ __forceinline__ void compute_stage_f32B(uint32_t Abase, const float* Bp,
                                                   float acc[2][8][4],
                                                   int wm, int wn,
                                                   uint32_t a_lane_off, int gid, int tig) {
#pragma unroll
    for (int s = 0; s < 4; ++s) {
        uint32_t af[2][4];
#pragma unroll
        for (int mi = 0; mi < 2; ++mi)
            ldsm4(af[mi], Abase + ((wm * 32 + mi * 16) * A_ROW_H + s * 16) * 2 + a_lane_off);
        const int k0 = s * 16;
        const float* B0 = Bp + (k0 + 2 * tig) * B_ROW_F;
        const float* B8 = B0 + 8 * B_ROW_F;
#pragma unroll
        for (int p = 0; p < 4; ++p) {
            int n0 = wn * 64 + p * 16 + gid;
            uint32_t b0a = pack2(B0[n0], B0[B_ROW_F + n0]);
            uint32_t b1a = pack2(B8[n0], B8[B_ROW_F + n0]);
            uint32_t b0b = pack2(B0[n0 + 8], B0[B_ROW_F + n0 + 8]);
            uint32_t b1b = pack2(B8[n0 + 8], B8[B_ROW_F + n0 + 8]);
#pragma unroll
            for (int mi = 0; mi < 2; ++mi) {
                mma16(acc[mi][2 * p],     af[mi][0], af[mi][1], af[mi][2], af[mi][3], b0a, b1a);
                mma16(acc[mi][2 * p + 1], af[mi][0], af[mi][1], af[mi][2], af[mi][3], b0b, b1b);
            }
        }
    }
}

__device__ __forceinline__ void compute_stage_f16B(uint32_t Abase, uint32_t Bbase,
                                                   float acc[2][8][4],
                                                   int wm, int wn,
                                                   uint32_t a_lane_off, uint32_t b_lane_off) {
#pragma unroll
    for (int s = 0; s < 4; ++s) {
        uint32_t af[2][4];
#pragma unroll
        for (int mi = 0; mi < 2; ++mi)
            ldsm4(af[mi], Abase + ((wm * 32 + mi * 16) * A_ROW_H + s * 16) * 2 + a_lane_off);
#pragma unroll
        for (int p = 0; p < 4; ++p) {
            uint32_t br[4];
            ldsm4t(br, Bbase + (s * 16 * B_ROW_H + wn * 64 + p * 16) * 2 + b_lane_off);
#pragma unroll
            for (int mi = 0; mi < 2; ++mi) {
                mma16(acc[mi][2 * p],     af[mi][0], af[mi][1], af[mi][2], af[mi][3], br[0], br[1]);
                mma16(acc[mi][2 * p + 1], af[mi][0], af[mi][1], af[mi][2], af[mi][3], br[2], br[3]);
            }
        }
    }
}

// ---------------------------------------------------------------------------
// Unified GEMM (fp16 m16n8k16, 64x256 tile, BK=64, 3 stages)
//   G1: fp32 W1 in-smem convert; piggybacks W2 fp32->fp16 global convert
//   G2: fp16 W2 from g_w2h (fast ldmatrix path)
// ---------------------------------------------------------------------------
template <bool G1>
__global__ __launch_bounds__(NTHREADS, 1) void gemm_kernel(const float* __restrict__ W,
                                                           const float* __restrict__ W2src,
                                                           const float* __restrict__ bias) {
    constexpr int B_STAGE_B = G1 ? B1_STAGE_BYTES : B2_STAGE_BYTES;
    constexpr int STAGE_B = A_STAGE_BYTES + B_STAGE_B;

    extern __shared__ uint32_t smx[];
    __shared__ int toks[BM];

    const int tid = threadIdx.x;
    int te = g_tile_expert[blockIdx.x];

    if (G1) {
        // piggyback W2 conversion: dead CTAs convert then exit
        if (te < 0) {
            convert_w2_slice(W2src, blockIdx.x + gridDim.x * blockIdx.y, tid);
            return;
        }
    } else if (te < 0) {
        return;
    }

    if (tid < BM) toks[tid] = g_perm[blockIdx.x * BM + tid];
    __syncthreads();

    const int split = G1 ? 0 : blockIdx.z;
    const int nbase = blockIdx.y * BN;
    const int lane = tid & 31, wid = tid >> 5;    // 8 warps
    const int wm = wid & 1, wn = wid >> 1;        // 2M x 4N, warp 32x64
    const int gid = lane >> 2, tig = lane & 3;

    const int ncb = G1 ? (D_DIM / BK) : (H_DIM / BK / NSPLIT);   // 8 / 16
    const int cb0 = G1 ? 0 : split * ncb;

    uint32_t sbase = (uint32_t)__cvta_generic_to_shared(smx);

    const uint32_t a_lane_off = (((lane & 7) + ((lane >> 3) & 1) * 8) * A_ROW_H
                                 + ((lane >> 4) & 1) * 8) * 2;
    const uint32_t b_lane_off = (((lane & 7) + ((lane >> 3) & 1) * 8) * B_ROW_H
                                 + ((lane >> 4) & 1) * 8) * 2;

    // A cp.async: 2/thread
    const int a_r = tid >> 3, a_seg = tid & 7;
    const uint32_t* a_src[2]; bool a_val[2];
#pragma unroll
    for (int j = 0; j < 2; ++j) {
        int r = a_r + 32 * j;
        if (G1) {
            int tk = toks[r];
            a_val[j] = (tk >= 0);
            a_src[j] = g_xh + (size_t)(tk >= 0 ? tk : 0) * (D_DIM / 2) + a_seg * 4;
        } else {
            a_val[j] = true;
            a_src[j] = g_hh + ((size_t)blockIdx.x * BM + r) * (H_DIM / 2) + a_seg * 4;
        }
    }

    // B sources
    const float*    We1 = W + (size_t)te * W_PE;                // G1: fp32
    const uint32_t* We2 = g_w2h + (size_t)te * NW_PE;           // G2: fp16
    const int b1_kr = tid >> 6, b1_ns = tid & 63;               // fp32 mapping
    const int b2_kr = tid >> 5, b2_ns = tid & 31;               // fp16 mapping

    float acc[2][8][4];
#pragma unroll
    for (int i = 0; i < 2; i++)
#pragma unroll
        for (int j = 0; j < 8; j++)
#pragma unroll
            for (int k = 0; k < 4; k++) acc[i][j][k] = 0.f;

    auto issue = [&](int c) {
        int kb = cb0 + c;
        uint32_t st = sbase + (uint32_t)(c % STAGES) * STAGE_B;
#pragma unroll
        for (int j = 0; j < 2; ++j)
            cp16(st + ((a_r + 32 * j) * A_ROW_H + a_seg * 8) * 2,
                 a_src[j] + kb * 32, a_val[j]);
        uint32_t bb = st + A_STAGE_BYTES;
        if (G1) {
#pragma unroll
            for (int j = 0; j < 16; ++j) {
                int kr = b1_kr + 4 * j;                        // 0..63
                cp16(bb + (kr * B_ROW_F + b1_ns * 4) * 4,
                     We1 + (size_t)(kb * 64 + kr) * H_DIM + nbase + b1_ns * 4, true);
            }
        } else {
#pragma unroll
            for (int j = 0; j < 8; ++j) {
                int kr = b2_kr + 8 * j;                        // 0..63
                cp16(bb + (kr * B_ROW_H + b2_ns * 8) * 2,
                     We2 + (size_t)(kb * 64 + kr) * (D_DIM / 2) + (nbase >> 1) + b2_ns * 4, true);
            }
        }
        cp_commit();
    };

    issue(0);
    issue(1);

    if (G1) {
        // overlap the W2 slice conversion with pipeline fill
        convert_w2_slice(W2src, blockIdx.x + gridDim.x * blockIdx.y, tid);
    }

    for (int c = 0; c < ncb; ++c) {
        cp_wait<STAGES - 2>();
        __syncthreads();
        if (c + STAGES - 1 < ncb) issue(c + STAGES - 1);
        uint32_t st = sbase + (uint32_t)(c % STAGES) * STAGE_B;
        if (G1) {
            const float* Bp = (const float*)((char*)smx + (c % STAGES) * STAGE_B + A_STAGE_BYTES);
            compute_stage_f32B(st, Bp, acc, wm, wn, a_lane_off, gid, tig);
        } else {
            compute_stage_f16B(st, st + A_STAGE_BYTES, acc, wm, wn, a_lane_off, b_lane_off);
        }
    }

    // ---- epilogue ----
    const float* be = bias + (size_t)te * (G1 ? H_DIM : D_DIM);
    if (G1) {
        int rowbase = blockIdx.x * BM;
#pragma unroll
        for (int ni = 0; ni < 8; ++ni) {
            int c0 = nbase + wn * 64 + ni * 8 + tig * 2;
            float bb0 = be[c0], bb1 = be[c0 + 1];
#pragma unroll
            for (int mi = 0; mi < 2; ++mi) {
                int r0 = rowbase + wm * 32 + mi * 16 + gid;
                g_hh[(size_t)r0 * (H_DIM / 2) + (c0 >> 1)] =
                    pack2(fmaxf(acc[mi][ni][0] + bb0, 0.f),
                          fmaxf(acc[mi][ni][1] + bb1, 0.f));
                g_hh[(size_t)(r0 + 8) * (H_DIM / 2) + (c0 >> 1)] =
                    pack2(fmaxf(acc[mi][ni][2] + bb0, 0.f),
                          fmaxf(acc[mi][ni][3] + bb1, 0.f));
            }
        }
    } else {
        float* dst = g_ffn[split];
#pragma unroll
        for (int ni = 0; ni < 8; ++ni) {
            int c0 = nbase + wn * 64 + ni * 8 + tig * 2;
            float bb0 = split == 0 ? be[c0] : 0.f;
            float bb1 = split == 0 ? be[c0 + 1] : 0.f;
#pragma unroll
            for (int mi = 0; mi < 2; ++mi) {
                int rl0 = wm * 32 + mi * 16 + gid;
                int tk0 = toks[rl0];
                int tk1 = toks[rl0 + 8];
                if (tk0 >= 0) {
                    float2 v;
                    v.x = acc[mi][ni][0] + bb0;
                    v.y = acc[mi][ni][1] + bb1;
                    *(float2*)(dst + (size_t)tk0 * D_DIM + c0) = v;
                }
                if (tk1 >= 0) {
                    float2 v;
                    v.x = acc[mi][ni][2] + bb0;
                    v.y = acc[mi][ni][3] + bb1;
                    *(float2*)(dst + (size_t)tk1 * D_DIM + c0) = v;
                }
            }
        }
    }
}

// ---------------------------------------------------------------------------
// Residual + LayerNorm (sums two split-K partials)
// ---------------------------------------------------------------------------
__global__ void ln_kernel(const float* __restrict__ x,
                          const float* __restrict__ gamma,
                          const float* __restrict__ beta,
                          float* __restrict__ out) {
    int t = blockIdx.x;
    int tid = threadIdx.x;  // 128
    size_t off = (size_t)t * D_DIM + tid * 4;

    float4 xv = *(const float4*)(x + off);
    float4 f0 = *(const float4*)(g_ffn[0] + off);
    float4 f1 = *(const float4*)(g_ffn[1] + off);
    float4 z;
    z.x = xv.x + f0.x + f1.x;
    z.y = xv.y + f0.y + f1.y;
    z.z = xv.z + f0.z + f1.z;
    z.w = xv.w + f0.w + f1.w;

    float s = z.x + z.y + z.z + z.w;
    float ss = z.x * z.x + z.y * z.y + z.z * z.z + z.w * z.w;
#pragma unroll
    for (int o = 16; o > 0; o >>= 1) {
        s += __shfl_xor_sync(0xffffffffu, s, o);
        ss += __shfl_xor_sync(0xffffffffu, ss, o);
    }
    __shared__ float sm[8];
    int w = tid >> 5;
    if ((tid & 31) == 0) { sm[w] = s; sm[4 + w] = ss; }
    __syncthreads();
    s = sm[0] + sm[1] + sm[2] + sm[3];
    ss = sm[4] + sm[5] + sm[6] + sm[7];

    float mean = s * (1.f / 512.f);
    float var = ss * (1.f / 512.f) - mean * mean;
    float rstd = rsqrtf(var + 1e-5f);

    float4 gv = *(const float4*)(gamma + tid * 4);
    float4 bv = *(const float4*)(beta + tid * 4);
    float4 o4;
    o4.x = (z.x - mean) * rstd * gv.x + bv.x;
    o4.y = (z.y - mean) * rstd * gv.y + bv.y;
    o4.z = (z.z - mean) * rstd * gv.z + bv.z;
    o4.w = (z.w - mean) * rstd * gv.w + bv.w;
    *(float4*)(out + off) = o4;
}

// ---------------------------------------------------------------------------
extern "C" void kernel_launch(void* const* d_in, const int* in_sizes, int n_in,
                              void* d_out, int out_size) {
    const float* x     = (const float*)d_in[0];
    const float* W1    = (const float*)d_in[1];
    const float* b1    = (const float*)d_in[2];
    const float* W2    = (const float*)d_in[3];
    const float* b2    = (const float*)d_in[4];
    const float* gamma = (const float*)d_in[5];
    const float* beta  = (const float*)d_in[6];
    const int*   orig  = (const int*)d_in[7];
    const int*   hmap  = (const int*)d_in[8];
    float* out = (float*)d_out;

    cudaFuncSetAttribute(gemm_kernel<true>, cudaFuncAttributeMaxDynamicSharedMemorySize, SMEM1_BYTES);
    cudaFuncSetAttribute(gemm_kernel<false>, cudaFuncAttributeMaxDynamicSharedMemorySize, SMEM2_BYTES);

    setup_kernel<<<1, 256>>>(orig, hmap);
    convert_x_kernel<<<(NW_X / 2 + 255) / 256, 256>>>(x);
    gemm_kernel<true><<<dim3(MAX_TILES, H_DIM / BN), NTHREADS, SMEM1_BYTES>>>(W1, W2, b1);
    gemm_kernel<false><<<dim3(MAX_TILES, D_DIM / BN, NSPLIT), NTHREADS, SMEM2_BYTES>>>(nullptr, nullptr, b2);
    ln_kernel<<<T_TOK, 128>>>(x, gamma, beta, out);
}